// round 1
// baseline (speedup 1.0000x reference)
#include <cuda_runtime.h>
#include <cuda_bf16.h>

// StructuralDistillationLoss: mean((aff(student) - aff(teacher))^2)
// aff = per-pixel L2-normalized channel vectors dotted with 3x3 neighbors (zero pad).
// Shapes fixed by the problem: B=8, C=64, H=W=128, fp32.
//
// Optimization: affinity is symmetric in (p, p+d); center tap contributes ~1e-14.
// So loss = 2 * sum over 4 half-offsets {(-1,-1),(-1,0),(-1,1),(0,-1)} / (B*9*H*W).

static constexpr int Cc = 64;
static constexpr int Hh = 128;
static constexpr int Ww = 128;
static constexpr int Bb = 8;

static constexpr int TX = 32;             // interior tile width  (one warp per row)
static constexpr int TY = 8;              // interior tile height
static constexpr int RCOLS = TX + 2;      // 34 (left halo + right halo for (-1,+1))
static constexpr int RROWS = TY + 1;      // 9  (top halo only; offsets all have dy<=0)
static constexpr int NP = RCOLS * RROWS;  // 306 region pixels
static constexpr int PPAD = 308;          // padded pixel stride in smem
static constexpr int CHUNK = 32;          // channels per smem chunk (2 chunks total)
static constexpr int NTHREADS = 256;

__device__ double g_sum;

__global__ void sdl_zero_kernel() { g_sum = 0.0; }

__global__ void __launch_bounds__(NTHREADS)
sdl_main_kernel(const float* __restrict__ sfeat, const float* __restrict__ tfeat) {
    __shared__ float buf[CHUNK * PPAD];   // raw feature chunk, [c][p] layout (39,424 B)
    __shared__ float ssq[PPAD];           // per-pixel sum of squares -> inv-norm
    __shared__ float wred[NTHREADS / 32];

    const int t  = threadIdx.x;
    const int tx = t & 31;
    const int ty = t >> 5;
    const int x0 = blockIdx.x * TX;
    const int y0 = blockIdx.y * TY;
    const int b  = blockIdx.z;

    // interior pixel index in region coordinates
    const int p = (ty + 1) * RCOLS + (tx + 1);

    // Precompute region-load coordinates: each thread loads region pixels q1=t, q2=t+256.
    const int q1  = t;
    const int r1  = q1 / RCOLS, c1 = q1 % RCOLS;
    const int gy1 = y0 - 1 + r1, gx1 = x0 - 1 + c1;
    const bool v1 = ((unsigned)gy1 < (unsigned)Hh) && ((unsigned)gx1 < (unsigned)Ww);
    const int off1 = gy1 * Ww + gx1;

    const int q2  = t + NTHREADS;
    const bool has2 = (q2 < NP);
    const int r2  = q2 / RCOLS, c2 = q2 % RCOLS;
    const int gy2 = y0 - 1 + r2, gx2 = x0 - 1 + c2;
    const bool v2 = has2 && ((unsigned)gy2 < (unsigned)Hh) && ((unsigned)gx2 < (unsigned)Ww);
    const int off2 = gy2 * Ww + gx2;

    float sa0 = 0.f, sa1 = 0.f, sa2 = 0.f, sa3 = 0.f;
    float local = 0.0f;

    const float* feats[2] = { sfeat, tfeat };

    #pragma unroll
    for (int which = 0; which < 2; ++which) {
        const float* fb = feats[which] + (size_t)b * Cc * Hh * Ww;
        float d0 = 0.f, d1 = 0.f, d2 = 0.f, d3 = 0.f;

        ssq[q1] = 0.f;
        if (has2) ssq[q2] = 0.f;
        __syncthreads();

        for (int c0 = 0; c0 < Cc; c0 += CHUNK) {
            const float* fc = fb + (size_t)c0 * Hh * Ww;
            // ---- load chunk: global (coalesced along W) -> smem [c][p] ----
            #pragma unroll
            for (int c = 0; c < CHUNK; ++c) {
                const float* fp = fc + (size_t)c * (Hh * Ww);
                buf[c * PPAD + q1] = v1 ? __ldg(fp + off1) : 0.f;
                if (has2) buf[c * PPAD + q2] = v2 ? __ldg(fp + off2) : 0.f;
            }
            __syncthreads();

            // ---- per-pixel sum of squares (whole region, incl. halo) ----
            {
                float s1 = 0.f, s2 = 0.f;
                #pragma unroll
                for (int c = 0; c < CHUNK; ++c) {
                    float a = buf[c * PPAD + q1];
                    s1 = fmaf(a, a, s1);
                    if (has2) { float a2v = buf[c * PPAD + q2]; s2 = fmaf(a2v, a2v, s2); }
                }
                ssq[q1] += s1;
                if (has2) ssq[q2] += s2;
            }

            // ---- raw dot products: center vs 4 half-offset neighbors ----
            #pragma unroll
            for (int c = 0; c < CHUNK; ++c) {
                const float* bc = buf + c * PPAD;
                float v = bc[p];
                d0 = fmaf(v, bc[p - RCOLS - 1], d0);
                d1 = fmaf(v, bc[p - RCOLS    ], d1);
                d2 = fmaf(v, bc[p - RCOLS + 1], d2);
                d3 = fmaf(v, bc[p - 1        ], d3);
            }
            __syncthreads();   // buf reused next chunk
        }

        // ---- convert ssq -> inverse norms (F.normalize eps semantics) ----
        ssq[q1] = 1.0f / fmaxf(sqrtf(ssq[q1]), 1e-12f);
        if (has2) ssq[q2] = 1.0f / fmaxf(sqrtf(ssq[q2]), 1e-12f);
        __syncthreads();

        const float invc = ssq[p];
        float a0 = d0 * invc * ssq[p - RCOLS - 1];
        float a1 = d1 * invc * ssq[p - RCOLS    ];
        float a2 = d2 * invc * ssq[p - RCOLS + 1];
        float a3 = d3 * invc * ssq[p - 1        ];

        if (which == 0) {
            sa0 = a0; sa1 = a1; sa2 = a2; sa3 = a3;
        } else {
            float e0 = sa0 - a0, e1 = sa1 - a1, e2 = sa2 - a2, e3 = sa3 - a3;
            local = fmaf(e0, e0, fmaf(e1, e1, fmaf(e2, e2, e3 * e3)));
        }
        __syncthreads();       // ssq / buf reused by next tensor
    }

    // ---- block reduction, one double atomic per block ----
    #pragma unroll
    for (int o = 16; o > 0; o >>= 1)
        local += __shfl_xor_sync(0xffffffffu, local, o);
    if ((t & 31) == 0) wred[t >> 5] = local;
    __syncthreads();
    if (t == 0) {
        float s = 0.f;
        #pragma unroll
        for (int w = 0; w < NTHREADS / 32; ++w) s += wred[w];
        atomicAdd(&g_sum, (double)s);
    }
}

__global__ void sdl_final_kernel(float* __restrict__ out) {
    // symmetry factor 2; divide by the reference's full element count B*9*H*W
    out[0] = (float)(2.0 * g_sum / (double)((long long)Bb * 9 * Hh * Ww));
}

extern "C" void kernel_launch(void* const* d_in, const int* in_sizes, int n_in,
                              void* d_out, int out_size) {
    const float* sfeat = (const float*)d_in[0];
    const float* tfeat = (const float*)d_in[1];
    float* out = (float*)d_out;

    sdl_zero_kernel<<<1, 1>>>();
    dim3 grid(Ww / TX, Hh / TY, Bb);   // (4, 16, 8) = 512 blocks
    sdl_main_kernel<<<grid, NTHREADS>>>(sfeat, tfeat);
    sdl_final_kernel<<<1, 1>>>(out);
}

// round 2
// speedup vs baseline: 1.0897x; 1.0897x over previous
#include <cuda_runtime.h>
#include <cuda_bf16.h>

// StructuralDistillationLoss: mean((aff(student) - aff(teacher))^2)
// aff = per-pixel L2-normalized channel vectors dotted with 3x3 neighbors (zero pad).
// Shapes fixed: B=8, C=64, H=W=128, fp32.
//
// Math: affinity is symmetric in (p, p+d); the center tap is identical for both
// tensors (||fn||^2) so its diff is ~0. loss = 2 * sum over the 4 half-offsets
// {(-1,-1),(-1,0),(-1,1),(0,-1)} of (sa-ta)^2, / (B*9*H*W).   [validated R1: rel_err 0.0]
//
// Single kernel: per-block partials + threadfence last-block reduction (saves
// ~8us of per-launch overhead vs 3 kernels). Norm accumulation lives in
// registers during the gmem load phase (no smem re-read pass).

static constexpr int Cc = 64;
static constexpr int Hh = 128;
static constexpr int Ww = 128;
static constexpr int Bb = 8;
static constexpr int HW = Hh * Ww;

static constexpr int TX = 32;             // interior tile width (one warp per row)
static constexpr int TY = 8;              // interior tile height
static constexpr int RCOLS = TX + 2;      // 34: left+right halo
static constexpr int RROWS = TY + 1;      // 9: top halo only (all offsets have dy<=0)
static constexpr int NP = RCOLS * RROWS;  // 306 region pixels
static constexpr int PPAD = 308;          // padded pixel stride in smem
static constexpr int CHUNK = 16;          // channels per smem chunk (4 chunks)
static constexpr int NTHREADS = 256;
static constexpr int NBLOCKS = (Ww / TX) * (Hh / TY) * Bb;  // 4*16*8 = 512

__device__ float g_partials[NBLOCKS];
__device__ unsigned int g_count;   // zero-initialized; last block resets to 0

__global__ void __launch_bounds__(NTHREADS)
sdl_kernel(const float* __restrict__ sfeat, const float* __restrict__ tfeat,
           float* __restrict__ out) {
    __shared__ float buf[CHUNK * PPAD];   // raw feature chunk, [c][p] (19,712 B)
    __shared__ float inv[PPAD];           // per-pixel inverse norms
    __shared__ float wred[NTHREADS / 32];
    __shared__ double dred[NTHREADS / 32];
    __shared__ bool  is_last;

    const int t  = threadIdx.x;
    const int tx = t & 31;
    const int ty = t >> 5;
    const int x0 = blockIdx.x * TX;
    const int y0 = blockIdx.y * TY;
    const int b  = blockIdx.z;

    const int p = (ty + 1) * RCOLS + (tx + 1);  // interior pixel, region coords

    // Region-load coordinates: thread t owns region pixels q1=t, q2=t+256.
    const int q1  = t;
    const int gy1 = y0 - 1 + q1 / RCOLS, gx1 = x0 - 1 + q1 % RCOLS;
    const bool v1 = ((unsigned)gy1 < (unsigned)Hh) && ((unsigned)gx1 < (unsigned)Ww);
    const int off1 = gy1 * Ww + gx1;

    const int q2  = t + NTHREADS;
    const bool has2 = (q2 < NP);
    const int gy2 = y0 - 1 + q2 / RCOLS, gx2 = x0 - 1 + q2 % RCOLS;
    const bool v2 = has2 && ((unsigned)gy2 < (unsigned)Hh) && ((unsigned)gx2 < (unsigned)Ww);
    const int off2 = gy2 * Ww + gx2;

    float sa0 = 0.f, sa1 = 0.f, sa2 = 0.f, sa3 = 0.f;
    float local = 0.0f;

    const float* feats[2] = { sfeat, tfeat };

    #pragma unroll
    for (int which = 0; which < 2; ++which) {
        const float* fb = feats[which] + (size_t)b * Cc * HW;
        const float* p1 = fb + off1;   // deref'd only when v1
        const float* p2 = fb + off2;   // deref'd only when v2
        float d0 = 0.f, d1 = 0.f, d2 = 0.f, d3 = 0.f;
        float s1 = 0.f, s2 = 0.f;      // per-pixel sum-of-squares (registers)

        for (int c0 = 0; c0 < Cc; c0 += CHUNK) {
            // ---- load chunk: gmem (coalesced along W) -> smem [c][p];
            //      fold Sum(v^2) into registers on the way through ----
            #pragma unroll
            for (int c = 0; c < CHUNK; ++c) {
                const int coff = (c0 + c) * HW;
                float v = v1 ? __ldg(p1 + coff) : 0.f;
                buf[c * PPAD + q1] = v;
                s1 = fmaf(v, v, s1);
                if (has2) {
                    float w = v2 ? __ldg(p2 + coff) : 0.f;
                    buf[c * PPAD + q2] = w;
                    s2 = fmaf(w, w, s2);
                }
            }
            __syncthreads();

            // ---- raw dots: center vs 4 half-offset neighbors ----
            #pragma unroll
            for (int c = 0; c < CHUNK; ++c) {
                const float* bc = buf + c * PPAD;
                float v = bc[p];
                d0 = fmaf(v, bc[p - RCOLS - 1], d0);
                d1 = fmaf(v, bc[p - RCOLS    ], d1);
                d2 = fmaf(v, bc[p - RCOLS + 1], d2);
                d3 = fmaf(v, bc[p - 1        ], d3);
            }
            __syncthreads();   // buf reused next chunk
        }

        // ---- inverse norms (F.normalize eps semantics) ----
        inv[q1] = 1.0f / fmaxf(sqrtf(s1), 1e-12f);
        if (has2) inv[q2] = 1.0f / fmaxf(sqrtf(s2), 1e-12f);
        __syncthreads();

        const float ic = inv[p];
        float a0 = d0 * ic * inv[p - RCOLS - 1];
        float a1 = d1 * ic * inv[p - RCOLS    ];
        float a2 = d2 * ic * inv[p - RCOLS + 1];
        float a3 = d3 * ic * inv[p - 1        ];

        if (which == 0) {
            sa0 = a0; sa1 = a1; sa2 = a2; sa3 = a3;
        } else {
            float e0 = sa0 - a0, e1 = sa1 - a1, e2 = sa2 - a2, e3 = sa3 - a3;
            local = fmaf(e0, e0, fmaf(e1, e1, fmaf(e2, e2, e3 * e3)));
        }
        // no extra sync needed: next tensor's first post-store __syncthreads
        // orders buf/inv reuse.
    }

    // ---- block reduction ----
    #pragma unroll
    for (int o = 16; o > 0; o >>= 1)
        local += __shfl_xor_sync(0xffffffffu, local, o);
    if (tx == 0) wred[ty] = local;
    __syncthreads();

    const int bid = (blockIdx.z * gridDim.y + blockIdx.y) * gridDim.x + blockIdx.x;
    if (t == 0) {
        float s = 0.f;
        #pragma unroll
        for (int w = 0; w < NTHREADS / 32; ++w) s += wred[w];
        g_partials[bid] = s;
        __threadfence();
        unsigned ticket = atomicAdd(&g_count, 1u);
        is_last = (ticket == (unsigned)(NBLOCKS - 1));
    }
    __syncthreads();

    // ---- last block: reduce all partials, write scalar, reset counter ----
    if (is_last) {
        double acc = (double)g_partials[t] + (double)g_partials[t + NTHREADS];
        #pragma unroll
        for (int o = 16; o > 0; o >>= 1)
            acc += __shfl_xor_sync(0xffffffffu, acc, o);
        if (tx == 0) dred[ty] = acc;
        __syncthreads();
        if (t == 0) {
            double tot = 0.0;
            #pragma unroll
            for (int w = 0; w < NTHREADS / 32; ++w) tot += dred[w];
            // symmetry factor 2; denominator = B*9*H*W
            out[0] = (float)(2.0 * tot / (double)((long long)Bb * 9 * HW));
            g_count = 0;   // reset for next graph replay
        }
    }
}

extern "C" void kernel_launch(void* const* d_in, const int* in_sizes, int n_in,
                              void* d_out, int out_size) {
    const float* sfeat = (const float*)d_in[0];
    const float* tfeat = (const float*)d_in[1];
    float* out = (float*)d_out;

    dim3 grid(Ww / TX, Hh / TY, Bb);   // (4, 16, 8) = 512 blocks
    sdl_kernel<<<grid, NTHREADS>>>(sfeat, tfeat, out);
}

// round 3
// speedup vs baseline: 1.6418x; 1.5066x over previous
#include <cuda_runtime.h>
#include <cuda_bf16.h>

// StructuralDistillationLoss: mean((aff(student) - aff(teacher))^2), B=8 C=64 H=W=128 fp32.
// Math (validated R1/R2, rel_err 0.0): affinity symmetric in (p,p+d), center tap cancels:
//   loss = 2 * sum over half-offsets {(-1,-1),(-1,0),(-1,1),(0,-1)} of (sa-ta)^2 / (B*9*H*W)
//
// R3: cp.async 3-stage pipeline (2-ahead prefetch, 1 sync/phase), both tensors per phase,
// norm accumulation folded into the dot loop via reader-ownership (no extra LDS).

static constexpr int Cc = 64, Hh = 128, Ww = 128, Bb = 8;
static constexpr int HW = Hh * Ww;

static constexpr int TX = 32, TY = 8;
static constexpr int RC = TX + 2;          // 34 region cols
static constexpr int RR = TY + 1;          // 9 region rows (top halo only)
static constexpr int NP = RC * RR;         // 306 region pixels
static constexpr int PPAD = 308;
static constexpr int CH = 8;               // channels per tensor per phase
static constexpr int NPH = Cc / CH;        // 8 phases
static constexpr int NSTG = 3;             // pipeline stages
static constexpr int NTHREADS = 256;
static constexpr int NBLOCKS = (Ww / TX) * (Hh / TY) * Bb;   // 512

static constexpr int BUF_FLOATS = NSTG * 2 * CH * PPAD;      // 14784
static constexpr int SMEM_FLOATS = BUF_FLOATS + 2 * PPAD;    // + inv arrays
static constexpr int SMEM_BYTES = SMEM_FLOATS * 4;           // 61600 B

__device__ float g_partials[NBLOCKS];
__device__ unsigned int g_count;   // zero-init; last block resets

__device__ __forceinline__ void cp4(unsigned dst, const float* src, int srcsz) {
    asm volatile("cp.async.ca.shared.global [%0], [%1], 4, %2;\n"
                 :: "r"(dst), "l"(src), "r"(srcsz));
}
__device__ __forceinline__ void cp_commit() {
    asm volatile("cp.async.commit_group;\n" ::: "memory");
}
__device__ __forceinline__ void cp_wait1() {
    asm volatile("cp.async.wait_group 1;\n" ::: "memory");
}

__global__ void __launch_bounds__(NTHREADS)
sdl_kernel(const float* __restrict__ sfeat, const float* __restrict__ tfeat,
           float* __restrict__ out) {
    extern __shared__ float sm[];
    float* buf  = sm;                  // [NSTG][2][CH][PPAD]
    float* invA = sm + BUF_FLOATS;     // [2][PPAD]
    __shared__ float  wred[NTHREADS / 32];
    __shared__ double dred[NTHREADS / 32];
    __shared__ bool   is_last;

    const int t  = threadIdx.x;
    const int tx = t & 31;
    const int ty = t >> 5;
    const int x0 = blockIdx.x * TX;
    const int y0 = blockIdx.y * TY;
    const int b  = blockIdx.z;

    const int p = (ty + 1) * RC + (tx + 1);   // interior pixel, region coords

    // region-load pixels owned by this thread
    const int q1  = t;
    const int gy1 = y0 - 1 + q1 / RC, gx1 = x0 - 1 + q1 % RC;
    const bool v1 = ((unsigned)gy1 < (unsigned)Hh) && ((unsigned)gx1 < (unsigned)Ww);
    const int off1 = v1 ? (gy1 * Ww + gx1) : 0;
    const int z1 = v1 ? 4 : 0;

    const int q2  = t + NTHREADS;
    const bool has2 = (q2 < NP);
    const int gy2 = y0 - 1 + q2 / RC, gx2 = x0 - 1 + q2 % RC;
    const bool v2 = has2 && ((unsigned)gy2 < (unsigned)Hh) && ((unsigned)gx2 < (unsigned)Ww);
    const int off2 = v2 ? (gy2 * Ww + gx2) : 0;
    const int z2 = v2 ? 4 : 0;

    const float* base[2] = { sfeat + (size_t)b * Cc * HW, tfeat + (size_t)b * Cc * HW };
    const unsigned buf_u32 = (unsigned)__cvta_generic_to_shared(buf);

    // issue cp.async loads of chunk k into stage stg
    auto issue = [&](int k, int stg) {
        const int cbase = k * CH;
        #pragma unroll
        for (int tens = 0; tens < 2; ++tens) {
            const float* src0 = base[tens] + (size_t)cbase * HW;
            unsigned drow = buf_u32 + (unsigned)(((stg * 2 + tens) * CH) * PPAD) * 4u;
            #pragma unroll
            for (int c = 0; c < CH; ++c) {
                cp4(drow + (unsigned)q1 * 4u, src0 + (size_t)c * HW + off1, z1);
                if (has2) cp4(drow + (unsigned)q2 * 4u, src0 + (size_t)c * HW + off2, z2);
                drow += (unsigned)PPAD * 4u;
            }
        }
    };

    // accumulators
    float d[2][4]  = {{0,0,0,0},{0,0,0,0}};
    float s0[2]  = {0,0};   // own pixel
    float sup[2] = {0,0};   // top-row halo     (ty==0 warps)
    float sl[2]  = {0,0};   // left-col halo    (tx==0 lanes)
    float sul[2] = {0,0};   // top-left corner  (tx==0 && ty==0)
    float sur[2] = {0,0};   // right-col halo   (tx==31 lanes)

    const bool wu_ty0 = (ty == 0);     // warp-uniform
    const bool l0  = (tx == 0);
    const bool l31 = (tx == 31);

    // ---- pipeline prologue: prefetch chunks 0,1 ----
    issue(0, 0); cp_commit();
    issue(1, 1); cp_commit();

    for (int k = 0; k < NPH; ++k) {
        cp_wait1();          // chunk k landed (only chunk k+1 may be outstanding)
        __syncthreads();     // data visible to all; all done reading stage (k+2)%3
        if (k + 2 < NPH) issue(k + 2, (k + 2) % NSTG);
        cp_commit();         // unconditional: keep group numbering uniform

        const float* sbase = buf + (k % NSTG) * (2 * CH * PPAD);
        #pragma unroll
        for (int tens = 0; tens < 2; ++tens) {
            const float* row = sbase + tens * CH * PPAD;
            #pragma unroll
            for (int c = 0; c < CH; ++c) {
                float v  = row[p];
                float n0 = row[p - RC - 1];
                float n1 = row[p - RC];
                float n2 = row[p - RC + 1];
                float n3 = row[p - 1];
                d[tens][0] = fmaf(v, n0, d[tens][0]);
                d[tens][1] = fmaf(v, n1, d[tens][1]);
                d[tens][2] = fmaf(v, n2, d[tens][2]);
                d[tens][3] = fmaf(v, n3, d[tens][3]);
                s0[tens]   = fmaf(v, v, s0[tens]);
                if (wu_ty0) {
                    sup[tens] = fmaf(n1, n1, sup[tens]);
                    if (l0) sul[tens] = fmaf(n0, n0, sul[tens]);
                }
                if (l0)  sl[tens]  = fmaf(n3, n3, sl[tens]);
                if (l31) sur[tens] = fmaf(n2, n2, sur[tens]);
                row += PPAD;
            }
        }
    }

    // ---- inverse norms (F.normalize eps), reader-ownership coverage ----
    #pragma unroll
    for (int tens = 0; tens < 2; ++tens) {
        float* iv = invA + tens * PPAD;
        iv[p] = 1.0f / fmaxf(sqrtf(s0[tens]), 1e-12f);
        if (wu_ty0) {
            iv[p - RC] = 1.0f / fmaxf(sqrtf(sup[tens]), 1e-12f);
            if (l0) iv[p - RC - 1] = 1.0f / fmaxf(sqrtf(sul[tens]), 1e-12f);
        }
        if (l0)  iv[p - 1]      = 1.0f / fmaxf(sqrtf(sl[tens]),  1e-12f);
        if (l31) iv[p - RC + 1] = 1.0f / fmaxf(sqrtf(sur[tens]), 1e-12f);
    }
    __syncthreads();

    // ---- combine: scaled affinities, squared diff over 4 half-offset taps ----
    const float* is_ = invA;
    const float* it_ = invA + PPAD;
    const int nbr[4] = { p - RC - 1, p - RC, p - RC + 1, p - 1 };
    const float ics = is_[p], ict = it_[p];
    float local = 0.f;
    #pragma unroll
    for (int j = 0; j < 4; ++j) {
        float as = d[0][j] * ics * is_[nbr[j]];
        float at = d[1][j] * ict * it_[nbr[j]];
        float e = as - at;
        local = fmaf(e, e, local);
    }

    // ---- block reduction ----
    #pragma unroll
    for (int o = 16; o > 0; o >>= 1)
        local += __shfl_xor_sync(0xffffffffu, local, o);
    if (tx == 0) wred[ty] = local;
    __syncthreads();

    const int bid = (blockIdx.z * gridDim.y + blockIdx.y) * gridDim.x + blockIdx.x;
    if (t == 0) {
        float s = 0.f;
        #pragma unroll
        for (int w = 0; w < NTHREADS / 32; ++w) s += wred[w];
        g_partials[bid] = s;
        __threadfence();
        unsigned ticket = atomicAdd(&g_count, 1u);
        is_last = (ticket == (unsigned)(NBLOCKS - 1));
    }
    __syncthreads();

    // ---- last block reduces partials, writes scalar, resets counter ----
    if (is_last) {
        double acc = (double)g_partials[t] + (double)g_partials[t + NTHREADS];
        #pragma unroll
        for (int o = 16; o > 0; o >>= 1)
            acc += __shfl_xor_sync(0xffffffffu, acc, o);
        if (tx == 0) dred[ty] = acc;
        __syncthreads();
        if (t == 0) {
            double tot = 0.0;
            #pragma unroll
            for (int w = 0; w < NTHREADS / 32; ++w) tot += dred[w];
            out[0] = (float)(2.0 * tot / (double)((long long)Bb * 9 * HW));
            g_count = 0;
        }
    }
}

extern "C" void kernel_launch(void* const* d_in, const int* in_sizes, int n_in,
                              void* d_out, int out_size) {
    const float* sfeat = (const float*)d_in[0];
    const float* tfeat = (const float*)d_in[1];
    float* out = (float*)d_out;

    cudaFuncSetAttribute(sdl_kernel,
                         cudaFuncAttributeMaxDynamicSharedMemorySize, SMEM_BYTES);
    dim3 grid(Ww / TX, Hh / TY, Bb);   // (4, 16, 8) = 512 blocks
    sdl_kernel<<<grid, NTHREADS, SMEM_BYTES>>>(sfeat, tfeat, out);
}

// round 4
// speedup vs baseline: 2.5336x; 1.5432x over previous
#include <cuda_runtime.h>
#include <cuda_bf16.h>

// StructuralDistillationLoss: mean((aff(student)-aff(teacher))^2), B=8 C=64 H=W=128 fp32.
// Math (validated R1-R3, rel_err 0.0): affinity symmetric in (p,p+d); center tap cancels:
//   loss = 2 * sum over half-offsets {(-1,-1),(-1,0),(-1,1),(0,-1)} of (sa-ta)^2 / (B*9*H*W)
//
// R4: full-width rows; warp = (tensor, interior-row, channel-half); lane = 4 adjacent px.
// 16B cp.async 3-stage pipeline; x-neighbors via warp shuffle (boundary zeros free);
// channel-split register accumulation, smem combine reusing the stage buffers.

static constexpr int Cc = 64, Hh = 128, Ww = 128, Bb = 8;
static constexpr int HW = Hh * Ww;

static constexpr int TY = 2;                  // interior rows per block
static constexpr int NROWS = TY + 1;          // 3 loaded rows (top halo only)
static constexpr int CH = 8;                  // channels per tensor per phase
static constexpr int NPH = Cc / CH;           // 8 phases
static constexpr int NSTG = 3;
static constexpr int NTHREADS = 256;
static constexpr int NBLOCKS = (Hh / TY) * Bb;            // 64*8 = 512

static constexpr int STAGE_FLOATS = 2 * CH * NROWS * Ww;  // 6144
static constexpr int SMEM_BYTES = NSTG * STAGE_FLOATS * 4; // 73728
static constexpr int NCP = 2 * CH * NROWS * (Ww / 4);     // 1536 float4 per phase
static constexpr int CPT = NCP / NTHREADS;                // 6 per thread, exact

__device__ float g_partials[NBLOCKS];
__device__ unsigned int g_count;   // zero-init; last block resets

__device__ __forceinline__ void cp16(unsigned dst, const float* src, int srcsz) {
    asm volatile("cp.async.ca.shared.global [%0], [%1], 16, %2;\n"
                 :: "r"(dst), "l"(src), "r"(srcsz));
}
__device__ __forceinline__ void cp_commit() {
    asm volatile("cp.async.commit_group;\n" ::: "memory");
}
__device__ __forceinline__ void cp_wait1() {
    asm volatile("cp.async.wait_group 1;\n" ::: "memory");
}

__global__ void __launch_bounds__(NTHREADS)
sdl_kernel(const float* __restrict__ sfeat, const float* __restrict__ tfeat,
           float* __restrict__ out) {
    extern __shared__ float sm[];   // [NSTG][2*CH][NROWS][128]; tail-reused for combine
    __shared__ float  wred[NTHREADS / 32];
    __shared__ double dred[NTHREADS / 32];
    __shared__ bool   is_last;

    const int t  = threadIdx.x;
    const int tx = t & 31;
    const int w  = t >> 5;
    const int T  = w & 1;          // tensor
    const int r  = (w >> 1) & 1;   // interior row within tile
    const int h  = w >> 2;         // channel half (0/1)
    const int y0 = blockIdx.x * TY;
    const int b  = blockIdx.y;

    const float* base[2] = { sfeat + (size_t)b * Cc * HW, tfeat + (size_t)b * Cc * HW };
    const unsigned smu = (unsigned)__cvta_generic_to_shared(sm);

    // ---- precompute the 6 cp.async slots this thread services every phase ----
    const float* ptr[CPT];
    unsigned     dst[CPT];
    int          zf[CPT];
    #pragma unroll
    for (int i = 0; i < CPT; ++i) {
        const int l    = t + i * NTHREADS;      // [0,1536)
        const int g    = l & 31;                // float4 granule in row
        const int row  = (l >> 5) % NROWS;      // 0..2
        const int cidx = l / (32 * NROWS);      // 0..15 = tensor*8+c
        const int tn   = cidx >> 3;
        const int c    = cidx & 7;
        const int gy   = y0 - 1 + row;
        const bool vld = ((unsigned)gy < (unsigned)Hh);
        ptr[i] = base[tn] + (size_t)c * HW + (vld ? gy * Ww : 0) + 4 * g;
        zf[i]  = vld ? 16 : 0;
        dst[i] = smu + (unsigned)(((cidx * NROWS + row) * Ww + 4 * g) * 4);
    }
    const unsigned stgB = (unsigned)(STAGE_FLOATS * 4);

    // dot accumulators: d[px 0..3][tap 0..3]; ssq for own row (sv) and halo row (su)
    float d[4][4] = {{0}};
    float sv[4] = {0, 0, 0, 0};
    float su[4] = {0, 0, 0, 0};

    // ---- prologue: prefetch chunks 0,1 ----
    #pragma unroll
    for (int i = 0; i < CPT; ++i) cp16(dst[i] + 0 * stgB, ptr[i], zf[i]);
    cp_commit();
    #pragma unroll
    for (int i = 0; i < CPT; ++i) cp16(dst[i] + 1 * stgB, ptr[i] + CH * HW, zf[i]);
    cp_commit();
    #pragma unroll
    for (int i = 0; i < CPT; ++i) ptr[i] += 2 * CH * HW;

    for (int k = 0; k < NPH; ++k) {
        cp_wait1();
        __syncthreads();
        if (k + 2 < NPH) {
            const unsigned soff = (unsigned)((k + 2) % NSTG) * stgB;
            #pragma unroll
            for (int i = 0; i < CPT; ++i) {
                cp16(dst[i] + soff, ptr[i], zf[i]);
                ptr[i] += CH * HW;
            }
        }
        cp_commit();

        const float* stg = sm + (k % NSTG) * STAGE_FLOATS;
        #pragma unroll
        for (int j = 0; j < 4; ++j) {
            const int cidx = T * CH + h * 4 + j;
            const float4 v4 = *reinterpret_cast<const float4*>(
                stg + (cidx * NROWS + 1 + r) * Ww + 4 * tx);
            const float4 u4 = *reinterpret_cast<const float4*>(
                stg + (cidx * NROWS + r) * Ww + 4 * tx);

            float ulm1 = __shfl_up_sync(0xffffffffu, u4.w, 1);
            float vlm1 = __shfl_up_sync(0xffffffffu, v4.w, 1);
            float up4  = __shfl_down_sync(0xffffffffu, u4.x, 1);
            if (tx == 0)  { ulm1 = 0.f; vlm1 = 0.f; }   // x = -1 zero pad
            if (tx == 31) { up4 = 0.f; }                // x = 128 zero pad

            // taps: 0=up-left 1=up 2=up-right 3=left
            d[0][0] = fmaf(v4.x, ulm1, d[0][0]);
            d[0][1] = fmaf(v4.x, u4.x, d[0][1]);
            d[0][2] = fmaf(v4.x, u4.y, d[0][2]);
            d[0][3] = fmaf(v4.x, vlm1, d[0][3]);

            d[1][0] = fmaf(v4.y, u4.x, d[1][0]);
            d[1][1] = fmaf(v4.y, u4.y, d[1][1]);
            d[1][2] = fmaf(v4.y, u4.z, d[1][2]);
            d[1][3] = fmaf(v4.y, v4.x, d[1][3]);

            d[2][0] = fmaf(v4.z, u4.y, d[2][0]);
            d[2][1] = fmaf(v4.z, u4.z, d[2][1]);
            d[2][2] = fmaf(v4.z, u4.w, d[2][2]);
            d[2][3] = fmaf(v4.z, v4.y, d[2][3]);

            d[3][0] = fmaf(v4.w, u4.z, d[3][0]);
            d[3][1] = fmaf(v4.w, u4.w, d[3][1]);
            d[3][2] = fmaf(v4.w, up4,  d[3][2]);
            d[3][3] = fmaf(v4.w, v4.z, d[3][3]);

            sv[0] = fmaf(v4.x, v4.x, sv[0]);
            sv[1] = fmaf(v4.y, v4.y, sv[1]);
            sv[2] = fmaf(v4.z, v4.z, sv[2]);
            sv[3] = fmaf(v4.w, v4.w, sv[3]);
            if (r == 0) {   // halo-row ssq (row y0-1)
                su[0] = fmaf(u4.x, u4.x, su[0]);
                su[1] = fmaf(u4.y, u4.y, su[1]);
                su[2] = fmaf(u4.z, u4.z, su[2]);
                su[3] = fmaf(u4.w, u4.w, su[3]);
            }
        }
    }
    __syncthreads();   // all stage reads done; reuse sm for combine

    // combine layout (aliases stage buffers):
    float* sdots = sm;          // [T][r][px128][slot2][tap4]  = 4096 floats
    float* sssq  = sm + 4096;   // [T][row3][slot2][px128]     = 1536 floats
    float* sinv  = sm + 5632;   // [T][row3][px128]            = 768 floats

    #pragma unroll
    for (int j = 0; j < 4; ++j) {
        *reinterpret_cast<float4*>(
            &sdots[((T * 2 + r) * Ww + 4 * tx + j) * 8 + h * 4]) =
            make_float4(d[j][0], d[j][1], d[j][2], d[j][3]);
    }
    *reinterpret_cast<float4*>(
        &sssq[((T * NROWS + (r + 1)) * 2 + h) * Ww + 4 * tx]) =
        make_float4(sv[0], sv[1], sv[2], sv[3]);
    if (r == 0) {
        *reinterpret_cast<float4*>(
            &sssq[((T * NROWS + 0) * 2 + h) * Ww + 4 * tx]) =
            make_float4(su[0], su[1], su[2], su[3]);
    }
    __syncthreads();

    // inverse norms: 768 entries, 3 per thread
    #pragma unroll
    for (int i = 0; i < 3; ++i) {
        const int e = t + i * NTHREADS;           // (T*3+row)*128 + x
        const int hi = e >> 7, x = e & 127;
        const float s = sssq[(hi << 8) + x] + sssq[(hi << 8) + 128 + x];
        sinv[e] = 1.0f / fmaxf(sqrtf(s), 1e-12f);
    }
    __syncthreads();

    // per-pixel affinity diff: thread -> (row rr, pixel x)
    const int rr = t >> 7, x = t & 127;
    const int xm = (x > 0) ? x - 1 : 0;           // dot is 0 there; clamp idx only
    const int xp = (x < 127) ? x + 1 : 127;
    float a[2][4];
    #pragma unroll
    for (int Ti = 0; Ti < 2; ++Ti) {
        const float4 da = *reinterpret_cast<const float4*>(
            &sdots[((Ti * 2 + rr) * Ww + x) * 8]);
        const float4 db = *reinterpret_cast<const float4*>(
            &sdots[((Ti * 2 + rr) * Ww + x) * 8 + 4]);
        const int ib = Ti * (NROWS * Ww);
        const float invC = sinv[ib + (rr + 1) * Ww + x];
        a[Ti][0] = (da.x + db.x) * invC * sinv[ib + rr * Ww + xm];
        a[Ti][1] = (da.y + db.y) * invC * sinv[ib + rr * Ww + x];
        a[Ti][2] = (da.z + db.z) * invC * sinv[ib + rr * Ww + xp];
        a[Ti][3] = (da.w + db.w) * invC * sinv[ib + (rr + 1) * Ww + xm];
    }
    float local = 0.f;
    #pragma unroll
    for (int j = 0; j < 4; ++j) {
        const float e = a[0][j] - a[1][j];
        local = fmaf(e, e, local);
    }

    // ---- block reduction ----
    #pragma unroll
    for (int o = 16; o > 0; o >>= 1)
        local += __shfl_xor_sync(0xffffffffu, local, o);
    if (tx == 0) wred[w] = local;
    __syncthreads();

    const int bid = blockIdx.y * gridDim.x + blockIdx.x;
    if (t == 0) {
        float s = 0.f;
        #pragma unroll
        for (int i = 0; i < NTHREADS / 32; ++i) s += wred[i];
        g_partials[bid] = s;
        __threadfence();
        unsigned ticket = atomicAdd(&g_count, 1u);
        is_last = (ticket == (unsigned)(NBLOCKS - 1));
    }
    __syncthreads();

    if (is_last) {
        double acc = (double)g_partials[t] + (double)g_partials[t + NTHREADS];
        #pragma unroll
        for (int o = 16; o > 0; o >>= 1)
            acc += __shfl_xor_sync(0xffffffffu, acc, o);
        if (tx == 0) dred[w] = acc;
        __syncthreads();
        if (t == 0) {
            double tot = 0.0;
            #pragma unroll
            for (int i = 0; i < NTHREADS / 32; ++i) tot += dred[i];
            out[0] = (float)(2.0 * tot / (double)((long long)Bb * 9 * HW));
            g_count = 0;
        }
    }
}

extern "C" void kernel_launch(void* const* d_in, const int* in_sizes, int n_in,
                              void* d_out, int out_size) {
    const float* sfeat = (const float*)d_in[0];
    const float* tfeat = (const float*)d_in[1];
    float* out = (float*)d_out;

    cudaFuncSetAttribute(sdl_kernel,
                         cudaFuncAttributeMaxDynamicSharedMemorySize, SMEM_BYTES);
    dim3 grid(Hh / TY, Bb);    // (64, 8) = 512 blocks
    sdl_kernel<<<grid, NTHREADS, SMEM_BYTES>>>(sfeat, tfeat, out);
}

// round 5
// speedup vs baseline: 2.7335x; 1.0789x over previous
#include <cuda_runtime.h>
#include <cuda_bf16.h>

// StructuralDistillationLoss: mean((aff(student)-aff(teacher))^2), B=8 C=64 H=W=128 fp32.
// Math (validated R1-R4, rel_err 0.0): affinity symmetric in (p,p+d); center tap cancels:
//   loss = 2 * sum over half-offsets {(-1,-1),(-1,0),(-1,1),(0,-1)} of (sa-ta)^2 / (B*9*H*W)
//
// R5: single-wave residency. CH=4, NSTG=4 (49.2KB smem), launch_bounds(256,4) caps regs
// at 64 -> 4 blocks/SM -> all 512 blocks resident in one wave (no tail wave).
// 16 phases, 3-ahead cp.async prefetch (wait_group 2), 16B copies, shuffle x-taps.

static constexpr int Cc = 64, Hh = 128, Ww = 128, Bb = 8;
static constexpr int HW = Hh * Ww;

static constexpr int TY = 2;                  // interior rows per block
static constexpr int NROWS = TY + 1;          // 3 loaded rows (top halo only)
static constexpr int CH = 4;                  // channels per tensor per phase
static constexpr int NPH = Cc / CH;           // 16 phases
static constexpr int NSTG = 4;
static constexpr int NTHREADS = 256;
static constexpr int NBLOCKS = (Hh / TY) * Bb;            // 512

static constexpr int STAGE_FLOATS = 2 * CH * NROWS * Ww;  // 3072
static constexpr int SMEM_BYTES = NSTG * STAGE_FLOATS * 4; // 49152
static constexpr int NCP = 2 * CH * NROWS * (Ww / 4);     // 768 float4 per phase
static constexpr int CPT = NCP / NTHREADS;                // 3 per thread, exact

__device__ float g_partials[NBLOCKS];
__device__ unsigned int g_count;   // zero-init; last block resets

__device__ __forceinline__ void cp16(unsigned dst, const float* src, int srcsz) {
    asm volatile("cp.async.ca.shared.global [%0], [%1], 16, %2;\n"
                 :: "r"(dst), "l"(src), "r"(srcsz));
}
__device__ __forceinline__ void cp_commit() {
    asm volatile("cp.async.commit_group;\n" ::: "memory");
}
__device__ __forceinline__ void cp_wait2() {
    asm volatile("cp.async.wait_group 2;\n" ::: "memory");
}

__global__ void __launch_bounds__(NTHREADS, 4)
sdl_kernel(const float* __restrict__ sfeat, const float* __restrict__ tfeat,
           float* __restrict__ out) {
    extern __shared__ float sm[];   // [NSTG][2*CH][NROWS][128]; tail-reused for combine
    __shared__ float  wred[NTHREADS / 32];
    __shared__ double dred[NTHREADS / 32];
    __shared__ bool   is_last;

    const int t  = threadIdx.x;
    const int tx = t & 31;
    const int w  = t >> 5;
    const int T  = w & 1;          // tensor
    const int r  = (w >> 1) & 1;   // interior row within tile
    const int h  = w >> 2;         // channel half (0/1), 2 channels each per phase
    const int y0 = blockIdx.x * TY;
    const int b  = blockIdx.y;

    const float* base[2] = { sfeat + (size_t)b * Cc * HW, tfeat + (size_t)b * Cc * HW };
    const unsigned smu = (unsigned)__cvta_generic_to_shared(sm);

    // ---- the 3 cp.async slots this thread services every phase ----
    const float* ptr[CPT];
    unsigned     dst[CPT];
    int          zf[CPT];
    #pragma unroll
    for (int i = 0; i < CPT; ++i) {
        const int l    = t + i * NTHREADS;      // [0,768)
        const int g    = l & 31;                // float4 granule in row
        const int row  = (l >> 5) % NROWS;      // 0..2
        const int cidx = l / (32 * NROWS);      // 0..7 = tensor*4+c
        const int tn   = cidx >> 2;
        const int c    = cidx & 3;
        const int gy   = y0 - 1 + row;
        const bool vld = ((unsigned)gy < (unsigned)Hh);
        ptr[i] = base[tn] + (size_t)c * HW + (vld ? gy * Ww : 0) + 4 * g;
        zf[i]  = vld ? 16 : 0;
        dst[i] = smu + (unsigned)(((cidx * NROWS + row) * Ww + 4 * g) * 4);
    }
    const unsigned stgB = (unsigned)(STAGE_FLOATS * 4);

    float d[4][4] = {{0}};
    float sv[4] = {0, 0, 0, 0};
    float su[4] = {0, 0, 0, 0};

    // ---- prologue: prefetch chunks 0,1,2 ----
    #pragma unroll
    for (int s = 0; s < 3; ++s) {
        #pragma unroll
        for (int i = 0; i < CPT; ++i)
            cp16(dst[i] + (unsigned)s * stgB, ptr[i] + (size_t)s * CH * HW, zf[i]);
        cp_commit();
    }
    #pragma unroll
    for (int i = 0; i < CPT; ++i) ptr[i] += 3 * (size_t)CH * HW;

    for (int k = 0; k < NPH; ++k) {
        cp_wait2();          // chunk k landed; k+1,k+2 may be outstanding
        __syncthreads();     // visible to all; stage (k+3)%4 (=(k-1)%4) free
        if (k + 3 < NPH) {
            const unsigned soff = (unsigned)((k + 3) % NSTG) * stgB;
            #pragma unroll
            for (int i = 0; i < CPT; ++i) {
                cp16(dst[i] + soff, ptr[i], zf[i]);
                ptr[i] += CH * HW;
            }
        }
        cp_commit();         // unconditional: uniform group numbering

        const float* stg = sm + (k % NSTG) * STAGE_FLOATS;
        #pragma unroll
        for (int j = 0; j < 2; ++j) {
            const int cidx = T * CH + h * 2 + j;
            const float4 v4 = *reinterpret_cast<const float4*>(
                stg + (cidx * NROWS + 1 + r) * Ww + 4 * tx);
            const float4 u4 = *reinterpret_cast<const float4*>(
                stg + (cidx * NROWS + r) * Ww + 4 * tx);

            float ulm1 = __shfl_up_sync(0xffffffffu, u4.w, 1);
            float vlm1 = __shfl_up_sync(0xffffffffu, v4.w, 1);
            float up4  = __shfl_down_sync(0xffffffffu, u4.x, 1);
            if (tx == 0)  { ulm1 = 0.f; vlm1 = 0.f; }   // x = -1 zero pad
            if (tx == 31) { up4 = 0.f; }                // x = 128 zero pad

            // taps: 0=up-left 1=up 2=up-right 3=left
            d[0][0] = fmaf(v4.x, ulm1, d[0][0]);
            d[0][1] = fmaf(v4.x, u4.x, d[0][1]);
            d[0][2] = fmaf(v4.x, u4.y, d[0][2]);
            d[0][3] = fmaf(v4.x, vlm1, d[0][3]);

            d[1][0] = fmaf(v4.y, u4.x, d[1][0]);
            d[1][1] = fmaf(v4.y, u4.y, d[1][1]);
            d[1][2] = fmaf(v4.y, u4.z, d[1][2]);
            d[1][3] = fmaf(v4.y, v4.x, d[1][3]);

            d[2][0] = fmaf(v4.z, u4.y, d[2][0]);
            d[2][1] = fmaf(v4.z, u4.z, d[2][1]);
            d[2][2] = fmaf(v4.z, u4.w, d[2][2]);
            d[2][3] = fmaf(v4.z, v4.y, d[2][3]);

            d[3][0] = fmaf(v4.w, u4.z, d[3][0]);
            d[3][1] = fmaf(v4.w, u4.w, d[3][1]);
            d[3][2] = fmaf(v4.w, up4,  d[3][2]);
            d[3][3] = fmaf(v4.w, v4.z, d[3][3]);

            sv[0] = fmaf(v4.x, v4.x, sv[0]);
            sv[1] = fmaf(v4.y, v4.y, sv[1]);
            sv[2] = fmaf(v4.z, v4.z, sv[2]);
            sv[3] = fmaf(v4.w, v4.w, sv[3]);
            if (r == 0) {   // halo-row ssq (row y0-1)
                su[0] = fmaf(u4.x, u4.x, su[0]);
                su[1] = fmaf(u4.y, u4.y, su[1]);
                su[2] = fmaf(u4.z, u4.z, su[2]);
                su[3] = fmaf(u4.w, u4.w, su[3]);
            }
        }
    }
    __syncthreads();   // all stage reads done; reuse sm for combine

    // combine layout (aliases stage buffers, 6400 floats < 12288):
    float* sdots = sm;          // [T][r][px128][slot2][tap4]  = 4096 floats
    float* sssq  = sm + 4096;   // [T][row3][slot2][px128]     = 1536 floats
    float* sinv  = sm + 5632;   // [T][row3][px128]            = 768 floats

    #pragma unroll
    for (int j = 0; j < 4; ++j) {
        *reinterpret_cast<float4*>(
            &sdots[((T * 2 + r) * Ww + 4 * tx + j) * 8 + h * 4]) =
            make_float4(d[j][0], d[j][1], d[j][2], d[j][3]);
    }
    *reinterpret_cast<float4*>(
        &sssq[((T * NROWS + (r + 1)) * 2 + h) * Ww + 4 * tx]) =
        make_float4(sv[0], sv[1], sv[2], sv[3]);
    if (r == 0) {
        *reinterpret_cast<float4*>(
            &sssq[((T * NROWS + 0) * 2 + h) * Ww + 4 * tx]) =
            make_float4(su[0], su[1], su[2], su[3]);
    }
    __syncthreads();

    // inverse norms: 768 entries, 3 per thread
    #pragma unroll
    for (int i = 0; i < 3; ++i) {
        const int e = t + i * NTHREADS;           // (T*3+row)*128 + x
        const int hi = e >> 7, x = e & 127;
        const float s = sssq[(hi << 8) + x] + sssq[(hi << 8) + 128 + x];
        sinv[e] = 1.0f / fmaxf(sqrtf(s), 1e-12f);
    }
    __syncthreads();

    // per-pixel affinity diff: thread -> (row rr, pixel x)
    const int rr = t >> 7, x = t & 127;
    const int xm = (x > 0) ? x - 1 : 0;           // dot is 0 there; clamp idx only
    const int xp = (x < 127) ? x + 1 : 127;
    float a[2][4];
    #pragma unroll
    for (int Ti = 0; Ti < 2; ++Ti) {
        const float4 da = *reinterpret_cast<const float4*>(
            &sdots[((Ti * 2 + rr) * Ww + x) * 8]);
        const float4 db = *reinterpret_cast<const float4*>(
            &sdots[((Ti * 2 + rr) * Ww + x) * 8 + 4]);
        const int ib = Ti * (NROWS * Ww);
        const float invC = sinv[ib + (rr + 1) * Ww + x];
        a[Ti][0] = (da.x + db.x) * invC * sinv[ib + rr * Ww + xm];
        a[Ti][1] = (da.y + db.y) * invC * sinv[ib + rr * Ww + x];
        a[Ti][2] = (da.z + db.z) * invC * sinv[ib + rr * Ww + xp];
        a[Ti][3] = (da.w + db.w) * invC * sinv[ib + (rr + 1) * Ww + xm];
    }
    float local = 0.f;
    #pragma unroll
    for (int j = 0; j < 4; ++j) {
        const float e = a[0][j] - a[1][j];
        local = fmaf(e, e, local);
    }

    // ---- block reduction ----
    #pragma unroll
    for (int o = 16; o > 0; o >>= 1)
        local += __shfl_xor_sync(0xffffffffu, local, o);
    if (tx == 0) wred[w] = local;
    __syncthreads();

    const int bid = blockIdx.y * gridDim.x + blockIdx.x;
    if (t == 0) {
        float s = 0.f;
        #pragma unroll
        for (int i = 0; i < NTHREADS / 32; ++i) s += wred[i];
        g_partials[bid] = s;
        __threadfence();
        unsigned ticket = atomicAdd(&g_count, 1u);
        is_last = (ticket == (unsigned)(NBLOCKS - 1));
    }
    __syncthreads();

    if (is_last) {
        double acc = (double)g_partials[t] + (double)g_partials[t + NTHREADS];
        #pragma unroll
        for (int o = 16; o > 0; o >>= 1)
            acc += __shfl_xor_sync(0xffffffffu, acc, o);
        if (tx == 0) dred[w] = acc;
        __syncthreads();
        if (t == 0) {
            double tot = 0.0;
            #pragma unroll
            for (int i = 0; i < NTHREADS / 32; ++i) tot += dred[i];
            out[0] = (float)(2.0 * tot / (double)((long long)Bb * 9 * HW));
            g_count = 0;
        }
    }
}

extern "C" void kernel_launch(void* const* d_in, const int* in_sizes, int n_in,
                              void* d_out, int out_size) {
    const float* sfeat = (const float*)d_in[0];
    const float* tfeat = (const float*)d_in[1];
    float* out = (float*)d_out;

    cudaFuncSetAttribute(sdl_kernel,
                         cudaFuncAttributeMaxDynamicSharedMemorySize, SMEM_BYTES);
    dim3 grid(Hh / TY, Bb);    // (64, 8) = 512 blocks
    sdl_kernel<<<grid, NTHREADS, SMEM_BYTES>>>(sfeat, tfeat, out);
}

// round 7
// speedup vs baseline: 2.8670x; 1.0488x over previous
#include <cuda_runtime.h>
#include <cuda_bf16.h>

// StructuralDistillationLoss: mean((aff(student)-aff(teacher))^2), B=8 C=64 H=W=128 fp32.
// Math (validated R1-R5, rel_err 0.0): affinity symmetric in (p,p+d); center tap cancels:
//   loss = 2 * sum over half-offsets {(-1,-1),(-1,0),(-1,1),(0,-1)} of (sa-ta)^2 / (B*9*H*W)
//
// R6 (resubmit after infra failure): CH=8 double-buffered (NSTG=2, 49.2KB smem -> 4
// blocks/SM single wave), 8 fat phases (half the barrier/wait overhead of R5), factored
// cp.async addressing (no per-slot pointer arrays -> no spills at 64 regs).

static constexpr int Cc = 64, Hh = 128, Ww = 128, Bb = 8;
static constexpr int HW = Hh * Ww;

static constexpr int TY = 2;                  // interior rows per block
static constexpr int NROWS = TY + 1;          // 3 loaded rows (top halo only)
static constexpr int CH = 8;                  // channels per tensor per phase
static constexpr int NPH = Cc / CH;           // 8 phases
static constexpr int NTHREADS = 256;
static constexpr int NBLOCKS = (Hh / TY) * Bb;            // 512

static constexpr int STAGE_FLOATS = 2 * CH * NROWS * Ww;  // 6144
static constexpr int STAGE_BYTES  = STAGE_FLOATS * 4;     // 24576
static constexpr int SMEM_BYTES   = 2 * STAGE_BYTES;      // 49152
static constexpr int ROW_BYTES    = Ww * 4;               // 512
static constexpr int TENS_BYTES   = CH * NROWS * ROW_BYTES; // 12288

__device__ float g_partials[NBLOCKS];
__device__ unsigned int g_count;   // zero-init; last block resets

__device__ __forceinline__ void cp16(unsigned dst, const float* src, int srcsz) {
    asm volatile("cp.async.ca.shared.global [%0], [%1], 16, %2;\n"
                 :: "r"(dst), "l"(src), "r"(srcsz));
}
__device__ __forceinline__ void cp_commit() {
    asm volatile("cp.async.commit_group;\n" ::: "memory");
}
__device__ __forceinline__ void cp_wait0() {
    asm volatile("cp.async.wait_group 0;\n" ::: "memory");
}

__global__ void __launch_bounds__(NTHREADS, 4)
sdl_kernel(const float* __restrict__ sfeat, const float* __restrict__ tfeat,
           float* __restrict__ out) {
    extern __shared__ float sm[];   // [2][2*CH][NROWS][128]; tail-reused for combine
    __shared__ float  wred[NTHREADS / 32];
    __shared__ double dred[NTHREADS / 32];
    __shared__ bool   is_last;

    const int t  = threadIdx.x;
    const int tx = t & 31;
    const int w  = t >> 5;
    const int T  = w & 1;          // tensor
    const int r  = (w >> 1) & 1;   // interior row within tile
    const int h  = w >> 2;         // channel half (0/1), 4 channels each
    const int y0 = blockIdx.x * TY;
    const int b  = blockIdx.y;

    // ---- factored copy addressing: thread owns (channel c_own, granule g) ----
    const int c_own = t >> 5;      // 0..7
    const int g     = t & 31;      // float4 granule in row
    const float* pS = sfeat + (size_t)b * Cc * HW + (size_t)c_own * HW + 4 * g;
    const float* pT = tfeat + (size_t)b * Cc * HW + (size_t)c_own * HW + 4 * g;

    const bool top_ok = (y0 > 0);
    const int rowoff0 = top_ok ? (y0 - 1) * Ww : 0;   // clamped when invalid
    const int rowoff1 = y0 * Ww;
    const int rowoff2 = (y0 + 1) * Ww;                // y0+1 <= 127 always
    const int zf0 = top_ok ? 16 : 0;

    const unsigned smu = (unsigned)__cvta_generic_to_shared(sm);
    const unsigned dstbase = smu + (unsigned)((c_own * NROWS * Ww + 4 * g) * 4);

    auto issue = [&](int k, int s) {
        const float* a  = pS + (size_t)k * CH * HW;
        const float* bq = pT + (size_t)k * CH * HW;
        const unsigned db = dstbase + (unsigned)s * (unsigned)STAGE_BYTES;
        cp16(db,                               a  + rowoff0, zf0);
        cp16(db + ROW_BYTES,                   a  + rowoff1, 16);
        cp16(db + 2 * ROW_BYTES,               a  + rowoff2, 16);
        cp16(db + TENS_BYTES,                  bq + rowoff0, zf0);
        cp16(db + TENS_BYTES + ROW_BYTES,      bq + rowoff1, 16);
        cp16(db + TENS_BYTES + 2 * ROW_BYTES,  bq + rowoff2, 16);
    };

    float d[4][4] = {{0}};
    float sv[4] = {0, 0, 0, 0};
    float su[4] = {0, 0, 0, 0};

    // ---- prologue: prefetch chunk 0 ----
    issue(0, 0); cp_commit();

    for (int k = 0; k < NPH; ++k) {
        cp_wait0();          // chunk k landed (had a full phase in flight)
        __syncthreads();     // data visible; all threads done reading stage (k+1)&1
        if (k + 1 < NPH) { issue(k + 1, (k + 1) & 1); cp_commit(); }

        const float* stg = sm + (k & 1) * STAGE_FLOATS;
        #pragma unroll
        for (int j = 0; j < 4; ++j) {
            const int cidx = T * CH + h * 4 + j;
            const float4 v4 = *reinterpret_cast<const float4*>(
                stg + (cidx * NROWS + 1 + r) * Ww + 4 * tx);
            const float4 u4 = *reinterpret_cast<const float4*>(
                stg + (cidx * NROWS + r) * Ww + 4 * tx);

            float ulm1 = __shfl_up_sync(0xffffffffu, u4.w, 1);
            float vlm1 = __shfl_up_sync(0xffffffffu, v4.w, 1);
            float up4  = __shfl_down_sync(0xffffffffu, u4.x, 1);
            if (tx == 0)  { ulm1 = 0.f; vlm1 = 0.f; }   // x = -1 zero pad
            if (tx == 31) { up4 = 0.f; }                // x = 128 zero pad

            // taps: 0=up-left 1=up 2=up-right 3=left
            d[0][0] = fmaf(v4.x, ulm1, d[0][0]);
            d[0][1] = fmaf(v4.x, u4.x, d[0][1]);
            d[0][2] = fmaf(v4.x, u4.y, d[0][2]);
            d[0][3] = fmaf(v4.x, vlm1, d[0][3]);

            d[1][0] = fmaf(v4.y, u4.x, d[1][0]);
            d[1][1] = fmaf(v4.y, u4.y, d[1][1]);
            d[1][2] = fmaf(v4.y, u4.z, d[1][2]);
            d[1][3] = fmaf(v4.y, v4.x, d[1][3]);

            d[2][0] = fmaf(v4.z, u4.y, d[2][0]);
            d[2][1] = fmaf(v4.z, u4.z, d[2][1]);
            d[2][2] = fmaf(v4.z, u4.w, d[2][2]);
            d[2][3] = fmaf(v4.z, v4.y, d[2][3]);

            d[3][0] = fmaf(v4.w, u4.z, d[3][0]);
            d[3][1] = fmaf(v4.w, u4.w, d[3][1]);
            d[3][2] = fmaf(v4.w, up4,  d[3][2]);
            d[3][3] = fmaf(v4.w, v4.z, d[3][3]);

            sv[0] = fmaf(v4.x, v4.x, sv[0]);
            sv[1] = fmaf(v4.y, v4.y, sv[1]);
            sv[2] = fmaf(v4.z, v4.z, sv[2]);
            sv[3] = fmaf(v4.w, v4.w, sv[3]);
            if (r == 0) {   // halo-row ssq (row y0-1)
                su[0] = fmaf(u4.x, u4.x, su[0]);
                su[1] = fmaf(u4.y, u4.y, su[1]);
                su[2] = fmaf(u4.z, u4.z, su[2]);
                su[3] = fmaf(u4.w, u4.w, su[3]);
            }
        }
    }
    __syncthreads();   // all stage reads done; reuse sm for combine

    // combine layout (aliases stage buffers, 6400 floats < 12288):
    float* sdots = sm;          // [T][r][px128][slot2][tap4]  = 4096 floats
    float* sssq  = sm + 4096;   // [T][row3][slot2][px128]     = 1536 floats
    float* sinv  = sm + 5632;   // [T][row3][px128]            = 768 floats

    #pragma unroll
    for (int j = 0; j < 4; ++j) {
        *reinterpret_cast<float4*>(
            &sdots[((T * 2 + r) * Ww + 4 * tx + j) * 8 + h * 4]) =
            make_float4(d[j][0], d[j][1], d[j][2], d[j][3]);
    }
    *reinterpret_cast<float4*>(
        &sssq[((T * NROWS + (r + 1)) * 2 + h) * Ww + 4 * tx]) =
        make_float4(sv[0], sv[1], sv[2], sv[3]);
    if (r == 0) {
        *reinterpret_cast<float4*>(
            &sssq[((T * NROWS + 0) * 2 + h) * Ww + 4 * tx]) =
            make_float4(su[0], su[1], su[2], su[3]);
    }
    __syncthreads();

    // inverse norms: 768 entries, 3 per thread
    #pragma unroll
    for (int i = 0; i < 3; ++i) {
        const int e = t + i * NTHREADS;           // (T*3+row)*128 + x
        const int hi = e >> 7, x = e & 127;
        const float s = sssq[(hi << 8) + x] + sssq[(hi << 8) + 128 + x];
        sinv[e] = 1.0f / fmaxf(sqrtf(s), 1e-12f);
    }
    __syncthreads();

    // per-pixel affinity diff: thread -> (row rr, pixel x)
    const int rr = t >> 7, x = t & 127;
    const int xm = (x > 0) ? x - 1 : 0;           // dot is 0 there; clamp idx only
    const int xp = (x < 127) ? x + 1 : 127;
    float a[2][4];
    #pragma unroll
    for (int Ti = 0; Ti < 2; ++Ti) {
        const float4 da = *reinterpret_cast<const float4*>(
            &sdots[((Ti * 2 + rr) * Ww + x) * 8]);
        const float4 db = *reinterpret_cast<const float4*>(
            &sdots[((Ti * 2 + rr) * Ww + x) * 8 + 4]);
        const int ib = Ti * (NROWS * Ww);
        const float invC = sinv[ib + (rr + 1) * Ww + x];
        a[Ti][0] = (da.x + db.x) * invC * sinv[ib + rr * Ww + xm];
        a[Ti][1] = (da.y + db.y) * invC * sinv[ib + rr * Ww + x];
        a[Ti][2] = (da.z + db.z) * invC * sinv[ib + rr * Ww + xp];
        a[Ti][3] = (da.w + db.w) * invC * sinv[ib + (rr + 1) * Ww + xm];
    }
    float local = 0.f;
    #pragma unroll
    for (int j = 0; j < 4; ++j) {
        const float e = a[0][j] - a[1][j];
        local = fmaf(e, e, local);
    }

    // ---- block reduction ----
    #pragma unroll
    for (int o = 16; o > 0; o >>= 1)
        local += __shfl_xor_sync(0xffffffffu, local, o);
    if (tx == 0) wred[w] = local;
    __syncthreads();

    const int bid = blockIdx.y * gridDim.x + blockIdx.x;
    if (t == 0) {
        float s = 0.f;
        #pragma unroll
        for (int i = 0; i < NTHREADS / 32; ++i) s += wred[i];
        g_partials[bid] = s;
        __threadfence();
        unsigned ticket = atomicAdd(&g_count, 1u);
        is_last = (ticket == (unsigned)(NBLOCKS - 1));
    }
    __syncthreads();

    if (is_last) {
        double acc = (double)g_partials[t] + (double)g_partials[t + NTHREADS];
        #pragma unroll
        for (int o = 16; o > 0; o >>= 1)
            acc += __shfl_xor_sync(0xffffffffu, acc, o);
        if (tx == 0) dred[w] = acc;
        __syncthreads();
        if (t == 0) {
            double tot = 0.0;
            #pragma unroll
            for (int i = 0; i < NTHREADS / 32; ++i) tot += dred[i];
            out[0] = (float)(2.0 * tot / (double)((long long)Bb * 9 * HW));
            g_count = 0;
        }
    }
}

extern "C" void kernel_launch(void* const* d_in, const int* in_sizes, int n_in,
                              void* d_out, int out_size) {
    const float* sfeat = (const float*)d_in[0];
    const float* tfeat = (const float*)d_in[1];
    float* out = (float*)d_out;

    cudaFuncSetAttribute(sdl_kernel,
                         cudaFuncAttributeMaxDynamicSharedMemorySize, SMEM_BYTES);
    dim3 grid(Hh / TY, Bb);    // (64, 8) = 512 blocks
    sdl_kernel<<<grid, NTHREADS, SMEM_BYTES>>>(sfeat, tfeat, out);
}